// round 1
// baseline (speedup 1.0000x reference)
#include <cuda_runtime.h>
#include <math.h>

// Problem constants
#define NB    64
#define NH    512
#define NW    512
#define NPTS  200

// ---------------- scratch (device globals, no allocation) ----------------
__device__ unsigned g_minb[NB];
__device__ unsigned g_maxb[NB];
// g_cnt[half][batch][row]: half 0 = cols [0,256) (contour 1),
//                          half 1 = cols [256,512) (contour 2, reversed image)
__device__ float g_cnt[2][NB][NH];

// ---------------- K0: reset atomics ----------------
__global__ void k0_init() {
    int i = threadIdx.x;
    if (i < NB) {
        g_minb[i] = 0x7f800000u;  // +inf bits
        g_maxb[i] = 0u;           // 0.0f bits (input is uniform(0,1), nonneg)
    }
}

// ---------------- K1: per-batch min/max of channel 1 ----------------
// grid (16, 64), block 256. Each block handles 8192 float4 (16384 pixels).
__global__ void k1_minmax(const float4* __restrict__ in) {
    int b = blockIdx.y;
    int chunk = blockIdx.x;
    const float4* p = in + (size_t)b * (NH * NW * 2 / 4) + (size_t)chunk * 8192;
    int t = threadIdx.x;
    float mn = 1e30f, mx = -1e30f;
#pragma unroll
    for (int i = 0; i < 32; i++) {
        float4 v = p[t + i * 256];
        mn = fminf(mn, fminf(v.y, v.w));   // .y/.w are channel-1 of two pixels
        mx = fmaxf(mx, fmaxf(v.y, v.w));
    }
#pragma unroll
    for (int o = 16; o; o >>= 1) {
        mn = fminf(mn, __shfl_xor_sync(0xffffffffu, mn, o));
        mx = fmaxf(mx, __shfl_xor_sync(0xffffffffu, mx, o));
    }
    __shared__ float smn[8], smx[8];
    int w = t >> 5;
    if ((t & 31) == 0) { smn[w] = mn; smx[w] = mx; }
    __syncthreads();
    if (t == 0) {
#pragma unroll
        for (int i = 1; i < 8; i++) { mn = fminf(mn, smn[i]); mx = fmaxf(mx, smx[i]); }
        atomicMin(&g_minb[b], __float_as_uint(mn));
        atomicMax(&g_maxb[b], __float_as_uint(mx));
    }
}

// ---------------- K2: per-row threshold counts, left & right half ----------------
// One warp per row. grid 4096, block 256 (8 warps).
__global__ void k2_count(const float4* __restrict__ in) {
    int gwarp = (blockIdx.x * blockDim.x + threadIdx.x) >> 5;  // 0..32767
    int lane  = threadIdx.x & 31;
    int b   = gwarp >> 9;
    int row = gwarp & 511;

    float mn = __uint_as_float(g_minb[b]);
    float mx = __uint_as_float(g_maxb[b]);
    float h  = 0.5f * (mx - mn);   // pred=1  <=>  (v-mn) > 0.5*(mx-mn)

    const float4* p = in + ((size_t)(b * NH + row)) * 256;  // 256 float4 per row
    unsigned cL = 0, cR = 0;
#pragma unroll
    for (int i = 0; i < 8; i++) {
        float4 v = p[lane + i * 32];
        unsigned c = (unsigned)((v.y - mn) > h) + (unsigned)((v.w - mn) > h);
        if (i < 4) cL += c; else cR += c;   // float4 idx <128 -> cols <256
    }
    cL = __reduce_add_sync(0xffffffffu, cL);
    cR = __reduce_add_sync(0xffffffffu, cR);
    if (lane == 0) {
        g_cnt[0][b][row] = (float)cL;
        g_cnt[1][b][row] = (float)cR;
    }
}

// ---------------- K3: per (batch, contour) resampling ----------------
// grid 128 (= batch*2), block 512.
__global__ void k3_contour(float* __restrict__ out) {
    const float TWO_PI = 6.283185307179586f;
    const float TT0    = (float)(M_PI / 2.0);
    const float DT     = (float)(M_PI / 200.0);

    int unit = blockIdx.x;
    int b = unit >> 1, c = unit & 1;
    int tid = threadIdx.x;  // == row for phase 1

    __shared__ float s_r[NH];
    __shared__ float s_tt[NH];
    __shared__ float s_red[16];
    __shared__ float s_bounds[2];

    float x1 = g_cnt[c][b][tid];
    float xa = fminf(x1, 1.0f);

    // block reduce xa: warps 0..7 cover rows 0..255 (top), 8..15 bottom
    float s = xa;
#pragma unroll
    for (int o = 16; o; o >>= 1) s += __shfl_xor_sync(0xffffffffu, s, o);
    if ((tid & 31) == 0) s_red[tid >> 5] = s;
    __syncthreads();
    if (tid == 0) {
        float st = 0.f, sb = 0.f;
#pragma unroll
        for (int i = 0; i < 8; i++)  st += s_red[i];
#pragma unroll
        for (int i = 8; i < 16; i++) sb += s_red[i];
        s_bounds[0] = 256.0f - st;   // ythtop
        s_bounds[1] = 256.0f + sb;   // ythbottom
    }
    __syncthreads();
    float top = s_bounds[0], bot = s_bounds[1];

    float y1 = fminf(fmaxf((float)tid, top), bot);
    float yc = y1 - 256.0f;
    float xc = -x1;
    s_r[tid] = sqrtf(xc * xc + yc * yc);
    float tt = atan2f(yc, xc);
    if (tt < 0.0f) tt += TWO_PI;     // fix_radians: map to [0, 2pi)
    s_tt[tid] = tt;
    __syncthreads();

    // 2 threads per output point; each covers 256 source rows x 3 period offsets.
    // All 512 threads execute (warps stay full for shfl); extras write nothing.
    int n = tid >> 1;               // 0..255 (only 0..199 real)
    int hh = tid & 1;
    float ttn = TT0 + (float)n * DT;
    float num = 0.f, den = 0.f;
    int base = hh << 8;
    for (int m = 0; m < 256; m++) {
        float t0 = s_tt[base + m];
        float r  = s_r[base + m];
#pragma unroll
        for (int q = 0; q < 3; q++) {
            float d  = t0 + (float)(q - 1) * TWO_PI - ttn;
            float d2 = fminf(d * d, 1.0f);
            float w  = __expf(-100.0f * d2);
            den += w;
            num = fmaf(w, r, num);
        }
    }
    num += __shfl_xor_sync(0xffffffffu, num, 1);
    den += __shfl_xor_sync(0xffffffffu, den, 1);

    if (hh == 0 && n < NPTS) {
        float rn = num / den;
        float x = fmaf(rn, cosf(ttn), 256.0f);
        float y = fmaf(rn, sinf(ttn), 256.0f);
        int idx; float xo;
        if (c == 0) { idx = n;        xo = x; }
        else        { idx = 399 - n;  xo = 512.0f - x; }
        out[((size_t)b * 400 + idx) * 2 + 0] = xo;
        out[((size_t)b * 400 + idx) * 2 + 1] = y;
    }
}

extern "C" void kernel_launch(void* const* d_in, const int* in_sizes, int n_in,
                              void* d_out, int out_size) {
    const float4* in = (const float4*)d_in[0];
    float* out = (float*)d_out;

    k0_init<<<1, 64>>>();
    k1_minmax<<<dim3(16, 64), 256>>>(in);
    k2_count<<<4096, 256>>>(in);
    k3_contour<<<128, 512>>>(out);
}